// round 1
// baseline (speedup 1.0000x reference)
#include <cuda_runtime.h>
#include <math.h>

#define N_NODES 50000
#define N_EDGES 800000
#define F_INN   512
#define HID     128
#define N_CLS   40
#define EPS_V   0.3f

// ---------------- scratch (static device globals; no allocations) ----------
__device__ float g_raw[N_NODES * HID];
__device__ float g_hA [N_NODES * HID];
__device__ float g_hB [N_NODES * HID];
__device__ float g_p  [N_NODES];
__device__ float g_q  [N_NODES];
__device__ float g_nd [N_NODES];
__device__ float g_ew [N_EDGES];
__device__ int   g_esrc[N_EDGES];
__device__ int   g_indptr[N_NODES + 1];
__device__ int   g_cnt[N_NODES];
__device__ int   g_deg[N_NODES];
__device__ int   g_cursor[N_NODES];

// ---------------- CSR build ----------------
__global__ void k_zero_counts() {
    int i = blockIdx.x * blockDim.x + threadIdx.x;
    if (i < N_NODES) { g_cnt[i] = 0; g_deg[i] = 0; }
}

__global__ void k_count(const int* __restrict__ row, const int* __restrict__ col) {
    int e = blockIdx.x * blockDim.x + threadIdx.x;
    if (e < N_EDGES) {
        atomicAdd(&g_deg[row[e]], 1);
        atomicAdd(&g_cnt[col[e]], 1);
    }
}

__global__ void k_nd() {
    int i = blockIdx.x * blockDim.x + threadIdx.x;
    if (i < N_NODES) {
        int d = g_deg[i];
        g_nd[i] = rsqrtf((float)(d < 1 ? 1 : d));
    }
}

// single-block exclusive scan of g_cnt -> g_indptr (N=50000)
__global__ void k_scan() {
    __shared__ int sums[1024];
    int tid = threadIdx.x;
    const int n = N_NODES;
    int chunk = (n + 1023) / 1024;
    int start = tid * chunk;
    int end = start + chunk; if (end > n) end = n;
    int s = 0;
    for (int i = start; i < end; i++) s += g_cnt[i];
    sums[tid] = s;
    __syncthreads();
    for (int off = 1; off < 1024; off <<= 1) {
        int v = (tid >= off) ? sums[tid - off] : 0;
        __syncthreads();
        sums[tid] += v;
        __syncthreads();
    }
    int run = (tid == 0) ? 0 : sums[tid - 1];
    for (int i = start; i < end; i++) {
        g_indptr[i] = run;
        run += g_cnt[i];
    }
    if (tid == 1023) g_indptr[n] = sums[1023];
}

__global__ void k_cursor() {
    int i = blockIdx.x * blockDim.x + threadIdx.x;
    if (i < N_NODES) g_cursor[i] = g_indptr[i];
}

__global__ void k_scatter(const int* __restrict__ row, const int* __restrict__ col) {
    int e = blockIdx.x * blockDim.x + threadIdx.x;
    if (e < N_EDGES) {
        int r = row[e], c = col[e];
        int pos = atomicAdd(&g_cursor[c], 1);
        g_esrc[pos] = r;
        g_ew[pos] = g_nd[r] * g_nd[c];
    }
}

// ---------------- GEMM1: h = relu(x @ t1_w^T + b), [N,512]x[128,512]^T ----
#define BM 128
#define BN 128
#define BK 16
#define TM 8
#define TN 8

__global__ __launch_bounds__(256)
void k_gemm1(const float* __restrict__ A,      // x [n, 512]
             const float* __restrict__ W,      // t1_w [128, 512]
             const float* __restrict__ bias,   // [128]
             float* __restrict__ h, float* __restrict__ raw, int n) {
    __shared__ float As[BK][BM + 4];
    __shared__ float Bs[BK][BN + 4];

    int tid = threadIdx.x;
    int block_m = blockIdx.x * BM;
    int tx = tid % 16, ty = tid / 16;

    float acc[TM][TN];
    #pragma unroll
    for (int i = 0; i < TM; i++)
        #pragma unroll
        for (int j = 0; j < TN; j++) acc[i][j] = 0.f;

    int lRow = tid >> 2;            // 0..63
    int lCol = (tid & 3) * 4;       // 0,4,8,12

    for (int k0 = 0; k0 < F_INN; k0 += BK) {
        #pragma unroll
        for (int r = 0; r < 2; r++) {
            int arow = block_m + lRow + r * 64;
            float4 v = make_float4(0.f, 0.f, 0.f, 0.f);
            if (arow < n) v = *(const float4*)&A[(size_t)arow * F_INN + k0 + lCol];
            As[lCol + 0][lRow + r * 64] = v.x;
            As[lCol + 1][lRow + r * 64] = v.y;
            As[lCol + 2][lRow + r * 64] = v.z;
            As[lCol + 3][lRow + r * 64] = v.w;

            int wrow = lRow + r * 64;  // 0..127
            float4 wv = *(const float4*)&W[(size_t)wrow * F_INN + k0 + lCol];
            Bs[lCol + 0][wrow] = wv.x;
            Bs[lCol + 1][wrow] = wv.y;
            Bs[lCol + 2][wrow] = wv.z;
            Bs[lCol + 3][wrow] = wv.w;
        }
        __syncthreads();

        #pragma unroll
        for (int kk = 0; kk < BK; kk++) {
            float a[TM], b[TN];
            const float4* ap = (const float4*)&As[kk][ty * TM];
            const float4* bp = (const float4*)&Bs[kk][tx * TN];
            float4 a0 = ap[0], a1 = ap[1];
            float4 b0 = bp[0], b1 = bp[1];
            a[0]=a0.x; a[1]=a0.y; a[2]=a0.z; a[3]=a0.w;
            a[4]=a1.x; a[5]=a1.y; a[6]=a1.z; a[7]=a1.w;
            b[0]=b0.x; b[1]=b0.y; b[2]=b0.z; b[3]=b0.w;
            b[4]=b1.x; b[5]=b1.y; b[6]=b1.z; b[7]=b1.w;
            #pragma unroll
            for (int i = 0; i < TM; i++)
                #pragma unroll
                for (int j = 0; j < TN; j++)
                    acc[i][j] = fmaf(a[i], b[j], acc[i][j]);
        }
        __syncthreads();
    }

    float bv[TN];
    #pragma unroll
    for (int j = 0; j < TN; j++) bv[j] = bias[tx * TN + j];

    #pragma unroll
    for (int i = 0; i < TM; i++) {
        int rowi = block_m + ty * TM + i;
        if (rowi < n) {
            float v[TN];
            #pragma unroll
            for (int j = 0; j < TN; j++) v[j] = fmaxf(acc[i][j] + bv[j], 0.f);
            float4 v0 = make_float4(v[0], v[1], v[2], v[3]);
            float4 v1 = make_float4(v[4], v[5], v[6], v[7]);
            size_t off = (size_t)rowi * HID + tx * TN;
            *(float4*)&h[off]     = v0;
            *(float4*)&h[off + 4] = v1;
            *(float4*)&raw[off]     = v0;
            *(float4*)&raw[off + 4] = v1;
        }
    }
}

// ---------------- per-node gate dots: p[i]=h[i].gw1, q[i]=h[i].gw2 --------
__global__ __launch_bounds__(256)
void k_pq(const float* __restrict__ h, const float* __restrict__ gw) {
    int gt = blockIdx.x * blockDim.x + threadIdx.x;
    int warp = gt >> 5, lane = gt & 31;
    if (warp >= N_NODES) return;
    float4 hv = ((const float4*)h)[warp * 32 + lane];
    float4 w1 = ((const float4*)gw)[lane];
    float4 w2 = ((const float4*)gw)[32 + lane];
    float a = hv.x * w1.x + hv.y * w1.y + hv.z * w1.z + hv.w * w1.w;
    float b = hv.x * w2.x + hv.y * w2.y + hv.z * w2.z + hv.w * w2.w;
    #pragma unroll
    for (int o = 16; o > 0; o >>= 1) {
        a += __shfl_down_sync(0xffffffffu, a, o);
        b += __shfl_down_sync(0xffffffffu, b, o);
    }
    if (lane == 0) { g_p[warp] = a; g_q[warp] = b; }
}

// ---------------- gathered SpMM per layer: hn = EPS*raw + A(g) @ h --------
__global__ __launch_bounds__(256)
void k_agg(const float* __restrict__ h, float* __restrict__ hn,
           const float* __restrict__ gbp, int kidx) {
    int gt = blockIdx.x * blockDim.x + threadIdx.x;
    int warp = gt >> 5, lane = gt & 31;
    if (warp >= N_NODES) return;
    float gb = __ldg(&gbp[kidx]);
    int beg = g_indptr[warp], end = g_indptr[warp + 1];
    float qc = g_q[warp];
    float4 r = ((const float4*)g_raw)[warp * 32 + lane];
    float4 acc = make_float4(EPS_V * r.x, EPS_V * r.y, EPS_V * r.z, EPS_V * r.w);
    const float4* h4 = (const float4*)h;

    for (int e = beg; e < end; e += 32) {
        int idx = e + lane;
        int src = 0; float nrm = 0.f;
        if (idx < end) {
            src = g_esrc[idx];
            nrm = tanhf(g_p[src] + qc + gb) * g_ew[idx];
        }
        int m = end - e; if (m > 32) m = 32;
        for (int j = 0; j < m; j++) {
            int   s  = __shfl_sync(0xffffffffu, src, j);
            float nm = __shfl_sync(0xffffffffu, nrm, j);
            float4 hv = h4[(size_t)s * 32 + lane];
            acc.x = fmaf(nm, hv.x, acc.x);
            acc.y = fmaf(nm, hv.y, acc.y);
            acc.z = fmaf(nm, hv.z, acc.z);
            acc.w = fmaf(nm, hv.w, acc.w);
        }
    }
    ((float4*)hn)[warp * 32 + lane] = acc;
}

// ---------------- classifier + log_softmax: [N,128]x[40,128]^T ------------
__global__ __launch_bounds__(320)
void k_out(const float* __restrict__ h, const float* __restrict__ w,
           const float* __restrict__ b, float* __restrict__ out, int n) {
    __shared__ float ws[N_CLS * HID];
    __shared__ float hs[8 * HID];
    __shared__ float logits[8 * N_CLS];
    int tid = threadIdx.x;
    for (int i = tid; i < N_CLS * HID; i += blockDim.x) ws[i] = w[i];
    int nodeBase = blockIdx.x * 8;
    for (int i = tid; i < 8 * HID; i += blockDim.x) {
        int nn = nodeBase + i / HID;
        hs[i] = (nn < n) ? h[(size_t)nn * HID + (i % HID)] : 0.f;
    }
    __syncthreads();

    int ln = tid / N_CLS;   // 0..7
    int c  = tid % N_CLS;   // 0..39
    float accv = b[c];
    const float4* hp = (const float4*)&hs[ln * HID];
    const float4* wp = (const float4*)&ws[c * HID];
    #pragma unroll
    for (int k = 0; k < HID / 4; k++) {
        float4 hv = hp[k], wv = wp[k];
        accv = fmaf(hv.x, wv.x, accv);
        accv = fmaf(hv.y, wv.y, accv);
        accv = fmaf(hv.z, wv.z, accv);
        accv = fmaf(hv.w, wv.w, accv);
    }
    logits[ln * N_CLS + c] = accv;
    __syncthreads();

    float mx = -1e30f;
    #pragma unroll 8
    for (int j = 0; j < N_CLS; j++) mx = fmaxf(mx, logits[ln * N_CLS + j]);
    float s = 0.f;
    #pragma unroll 8
    for (int j = 0; j < N_CLS; j++) s += expf(logits[ln * N_CLS + j] - mx);
    int nn = nodeBase + ln;
    if (nn < n) out[(size_t)nn * N_CLS + c] = accv - mx - logf(s);
}

// ---------------- host launcher ----------------
extern "C" void kernel_launch(void* const* d_in, const int* in_sizes, int n_in,
                              void* d_out, int out_size) {
    const float* x   = (const float*)d_in[0];
    const int*   ei  = (const int*)d_in[1];
    const float* t1w = (const float*)d_in[2];
    const float* t1b = (const float*)d_in[3];
    const float* gw  = (const float*)d_in[4];
    const float* gb  = (const float*)d_in[5];
    const float* t2w = (const float*)d_in[6];
    const float* t2b = (const float*)d_in[7];
    float* out = (float*)d_out;

    const int* row = ei;
    const int* col = ei + N_EDGES;

    float *hA, *hB, *raw;
    cudaGetSymbolAddress((void**)&hA,  g_hA);
    cudaGetSymbolAddress((void**)&hB,  g_hB);
    cudaGetSymbolAddress((void**)&raw, g_raw);

    // CSR build (rebuilt every launch; deterministic up to atomic ordering)
    k_zero_counts<<<(N_NODES + 255) / 256, 256>>>();
    k_count<<<(N_EDGES + 255) / 256, 256>>>(row, col);
    k_nd<<<(N_NODES + 255) / 256, 256>>>();
    k_scan<<<1, 1024>>>();
    k_cursor<<<(N_NODES + 255) / 256, 256>>>();
    k_scatter<<<(N_EDGES + 255) / 256, 256>>>(row, col);

    // h = relu(x @ t1_w^T + b); raw = h
    k_gemm1<<<(N_NODES + BM - 1) / BM, 256>>>(x, t1w, t1b, hA, raw, N_NODES);

    // 4 propagation layers (ping-pong hA/hB)
    float* cur = hA;
    float* nxt = hB;
    int warpBlocks = (N_NODES * 32 + 255) / 256;
    for (int k = 0; k < 4; k++) {
        k_pq<<<warpBlocks, 256>>>(cur, gw + (size_t)k * 2 * HID);
        k_agg<<<warpBlocks, 256>>>(cur, nxt, gb, k);
        float* t = cur; cur = nxt; nxt = t;
    }

    // classifier + log_softmax
    k_out<<<(N_NODES + 7) / 8, 320>>>(cur, t2w, t2b, out, N_NODES);
}

// round 3
// speedup vs baseline: 1.3064x; 1.3064x over previous
#include <cuda_runtime.h>
#include <cuda_bf16.h>
#include <math.h>
#include <stdint.h>

#define N_NODES 50000
#define N_EDGES 800000
#define F_INN   512
#define HID     128
#define N_CLS   40
#define EPS_V   0.3f

// ---------------- scratch (static device globals; no allocations) ----------
__device__ float g_raw[N_NODES * HID];
__device__ float g_hA [N_NODES * HID];
__device__ float g_hB [N_NODES * HID];
__device__ float g_p  [N_NODES];
__device__ float g_q  [N_NODES];
__device__ float g_nd [N_NODES];
__device__ float g_ew [N_EDGES];
__device__ int   g_esrc[N_EDGES];
__device__ int   g_indptr[N_NODES + 1];
__device__ int   g_cnt[N_NODES];
__device__ int   g_deg[N_NODES];
__device__ int   g_cursor[N_NODES];
__device__ int   g_bsum[256];
__device__ int   g_boff[256];

// ================= PTX helpers (ldmatrix / mma.sync — baseline sm_80+) =====
__device__ __forceinline__ uint32_t smem_u32(const void* p) {
    uint32_t a;
    asm("{ .reg .u64 t; cvta.to.shared.u64 t, %1; cvt.u32.u64 %0, t; }" : "=r"(a) : "l"(p));
    return a;
}
__device__ __forceinline__ void ldsm_x4(uint32_t (&r)[4], uint32_t addr) {
    asm volatile("ldmatrix.sync.aligned.m8n8.x4.shared.b16 {%0,%1,%2,%3}, [%4];"
        : "=r"(r[0]), "=r"(r[1]), "=r"(r[2]), "=r"(r[3]) : "r"(addr));
}
__device__ __forceinline__ void ldsm_x2(uint32_t (&r)[2], uint32_t addr) {
    asm volatile("ldmatrix.sync.aligned.m8n8.x2.shared.b16 {%0,%1}, [%2];"
        : "=r"(r[0]), "=r"(r[1]) : "r"(addr));
}
__device__ __forceinline__ void mma_bf16(float (&d)[4], const uint32_t (&a)[4], const uint32_t (&b)[2]) {
    asm volatile("mma.sync.aligned.m16n8k16.row.col.f32.bf16.bf16.f32 "
        "{%0,%1,%2,%3}, {%4,%5,%6,%7}, {%8,%9}, {%0,%1,%2,%3};"
        : "+f"(d[0]), "+f"(d[1]), "+f"(d[2]), "+f"(d[3])
        : "r"(a[0]), "r"(a[1]), "r"(a[2]), "r"(a[3]), "r"(b[0]), "r"(b[1]));
}
__device__ __forceinline__ uint32_t pack_bf16(float a, float b) {
    __nv_bfloat16 x = __float2bfloat16(a), y = __float2bfloat16(b);
    return (uint32_t)(*(uint16_t*)&x) | ((uint32_t)(*(uint16_t*)&y) << 16);
}

// ---------------- CSR build ----------------
__global__ void k_zero_counts() {
    int i = blockIdx.x * blockDim.x + threadIdx.x;
    if (i < N_NODES) { g_cnt[i] = 0; g_deg[i] = 0; }
}

__global__ void k_count(const int* __restrict__ row, const int* __restrict__ col) {
    int e = blockIdx.x * blockDim.x + threadIdx.x;
    if (e < N_EDGES) {
        atomicAdd(&g_deg[row[e]], 1);
        atomicAdd(&g_cnt[col[e]], 1);
    }
}

__global__ void k_nd() {
    int i = blockIdx.x * blockDim.x + threadIdx.x;
    if (i < N_NODES) {
        int d = g_deg[i];
        g_nd[i] = rsqrtf((float)(d < 1 ? 1 : d));
    }
}

// fast 3-kernel scan
__global__ void k_scan1() {
    __shared__ int s[256];
    int tid = threadIdx.x;
    int i = blockIdx.x * 256 + tid;
    int v = (i < N_NODES) ? g_cnt[i] : 0;
    s[tid] = v;
    __syncthreads();
    #pragma unroll
    for (int off = 1; off < 256; off <<= 1) {
        int t = (tid >= off) ? s[tid - off] : 0;
        __syncthreads();
        s[tid] += t;
        __syncthreads();
    }
    if (i < N_NODES) g_indptr[i] = s[tid] - v;
    if (tid == 255) g_bsum[blockIdx.x] = s[255];
}

__global__ void k_scan2(int nblocks) {
    __shared__ int s[256];
    int tid = threadIdx.x;
    int v = (tid < nblocks) ? g_bsum[tid] : 0;
    s[tid] = v;
    __syncthreads();
    #pragma unroll
    for (int off = 1; off < 256; off <<= 1) {
        int t = (tid >= off) ? s[tid - off] : 0;
        __syncthreads();
        s[tid] += t;
        __syncthreads();
    }
    g_boff[tid] = s[tid] - v;
    if (tid == 0) g_indptr[N_NODES] = N_EDGES;
}

__global__ void k_scan3() {
    int tid = threadIdx.x;
    int i = blockIdx.x * 256 + tid;
    if (i < N_NODES) {
        int ip = g_indptr[i] + g_boff[blockIdx.x];
        g_indptr[i] = ip;
        g_cursor[i] = ip;
    }
}

__global__ void k_scatter(const int* __restrict__ row, const int* __restrict__ col) {
    int e = blockIdx.x * blockDim.x + threadIdx.x;
    if (e < N_EDGES) {
        int r = row[e], c = col[e];
        int pos = atomicAdd(&g_cursor[c], 1);
        g_esrc[pos] = r;
        g_ew[pos] = g_nd[r] * g_nd[c];
    }
}

// ============ GEMM1 via mma.sync bf16 hi/lo split ==========================
// h = relu(x @ t1_w^T + b). C[m][n] = sum_k A[m][k] * W[n][k]
// CTA tile 128(M) x 128(N), BK=32 fp32 -> bf16 hi/lo smem tiles, stride 40.
#define TSTRIDE 40

__global__ __launch_bounds__(256)
void k_gemm1_mma(const float* __restrict__ A, const float* __restrict__ W,
                 const float* __restrict__ bias,
                 float* __restrict__ h, float* __restrict__ raw, int n) {
    __shared__ uint16_t As_hi[128 * TSTRIDE];
    __shared__ uint16_t As_lo[128 * TSTRIDE];
    __shared__ uint16_t Ws_hi[128 * TSTRIDE];
    __shared__ uint16_t Ws_lo[128 * TSTRIDE];
    __shared__ float sbias[HID];

    int tid = threadIdx.x;
    int wid = tid >> 5, lane = tid & 31;
    int warp_m = wid >> 2;        // 0..1 -> 64 rows
    int warp_n = wid & 3;         // 0..3 -> 32 cols
    int blockM = blockIdx.x * 128;

    if (tid < HID) sbias[tid] = bias[tid];

    uint32_t sAh = smem_u32(As_hi), sAl = smem_u32(As_lo);
    uint32_t sWh = smem_u32(Ws_hi), sWl = smem_u32(Ws_lo);

    float acc[4][4][4];
    #pragma unroll
    for (int i = 0; i < 4; i++)
        #pragma unroll
        for (int j = 0; j < 4; j++)
            #pragma unroll
            for (int k = 0; k < 4; k++) acc[i][j][k] = 0.f;

    // precomputed ldmatrix smem byte addresses (per-lane), col offset added later
    int a_row = (lane & 15), a_cblk = (lane >> 4) * 8;         // A frag
    int b_row = (lane & 7), b_cblk = ((lane >> 3) & 1) * 8;    // B frag (lanes 0-15 used)

    for (int k0 = 0; k0 < F_INN; k0 += 32) {
        // load + convert: 128 rows x 32 cols fp32 -> bf16 hi/lo
        #pragma unroll
        for (int it = 0; it < 4; it++) {
            int idx = tid + it * 256;     // 0..1023
            int r = idx >> 3;             // 0..127
            int c4 = (idx & 7) * 4;       // 0..28
            int soff = r * TSTRIDE + c4;

            int gr = blockM + r;
            float4 av = (gr < n) ? *(const float4*)&A[(size_t)gr * F_INN + k0 + c4]
                                 : make_float4(0.f, 0.f, 0.f, 0.f);
            float hx = __bfloat162float(__float2bfloat16(av.x));
            float hy = __bfloat162float(__float2bfloat16(av.y));
            float hz = __bfloat162float(__float2bfloat16(av.z));
            float hw = __bfloat162float(__float2bfloat16(av.w));
            *(uint2*)&As_hi[soff] = make_uint2(pack_bf16(av.x, av.y), pack_bf16(av.z, av.w));
            *(uint2*)&As_lo[soff] = make_uint2(pack_bf16(av.x - hx, av.y - hy), pack_bf16(av.z - hz, av.w - hw));

            float4 wv = *(const float4*)&W[(size_t)r * F_INN + k0 + c4];
            hx = __bfloat162float(__float2bfloat16(wv.x));
            hy = __bfloat162float(__float2bfloat16(wv.y));
            hz = __bfloat162float(__float2bfloat16(wv.z));
            hw = __bfloat162float(__float2bfloat16(wv.w));
            *(uint2*)&Ws_hi[soff] = make_uint2(pack_bf16(wv.x, wv.y), pack_bf16(wv.z, wv.w));
            *(uint2*)&Ws_lo[soff] = make_uint2(pack_bf16(wv.x - hx, wv.y - hy), pack_bf16(wv.z - hz, wv.w - hw));
        }
        __syncthreads();

        #pragma unroll
        for (int kk = 0; kk < 32; kk += 16) {
            // B fragments for this warp's 32-col strip (4 n-tiles)
            uint32_t bh[4][2], bl[4][2];
            #pragma unroll
            for (int nt = 0; nt < 4; nt++) {
                uint32_t boff = 2u * (uint32_t)((warp_n * 32 + nt * 8 + b_row) * TSTRIDE + kk + b_cblk);
                ldsm_x2(bh[nt], sWh + boff);
                ldsm_x2(bl[nt], sWl + boff);
            }
            #pragma unroll
            for (int mt = 0; mt < 4; mt++) {
                uint32_t aoff = 2u * (uint32_t)((warp_m * 64 + mt * 16 + a_row) * TSTRIDE + kk + a_cblk);
                uint32_t ah[4], al[4];
                ldsm_x4(ah, sAh + aoff);
                ldsm_x4(al, sAl + aoff);
                #pragma unroll
                for (int nt = 0; nt < 4; nt++) {
                    mma_bf16(acc[mt][nt], ah, bh[nt]);   // hi*hi
                    mma_bf16(acc[mt][nt], ah, bl[nt]);   // hi*lo
                    mma_bf16(acc[mt][nt], al, bh[nt]);   // lo*hi
                }
            }
        }
        __syncthreads();
    }

    // epilogue: bias + relu, write h and raw
    #pragma unroll
    for (int mt = 0; mt < 4; mt++) {
        int m0 = blockM + warp_m * 64 + mt * 16 + (lane >> 2);
        int m1 = m0 + 8;
        #pragma unroll
        for (int nt = 0; nt < 4; nt++) {
            int n0 = warp_n * 32 + nt * 8 + 2 * (lane & 3);
            float b0 = sbias[n0], b1 = sbias[n0 + 1];
            if (m0 < n) {
                float2 v = make_float2(fmaxf(acc[mt][nt][0] + b0, 0.f),
                                       fmaxf(acc[mt][nt][1] + b1, 0.f));
                *(float2*)&h[(size_t)m0 * HID + n0] = v;
                *(float2*)&raw[(size_t)m0 * HID + n0] = v;
            }
            if (m1 < n) {
                float2 v = make_float2(fmaxf(acc[mt][nt][2] + b0, 0.f),
                                       fmaxf(acc[mt][nt][3] + b1, 0.f));
                *(float2*)&h[(size_t)m1 * HID + n0] = v;
                *(float2*)&raw[(size_t)m1 * HID + n0] = v;
            }
        }
    }
}

// ---------------- per-node gate dots: p[i]=h[i].gw1, q[i]=h[i].gw2 --------
__global__ __launch_bounds__(256)
void k_pq(const float* __restrict__ h, const float* __restrict__ gw) {
    int gt = blockIdx.x * blockDim.x + threadIdx.x;
    int warp = gt >> 5, lane = gt & 31;
    if (warp >= N_NODES) return;
    float4 hv = ((const float4*)h)[warp * 32 + lane];
    float4 w1 = ((const float4*)gw)[lane];
    float4 w2 = ((const float4*)gw)[32 + lane];
    float a = hv.x * w1.x + hv.y * w1.y + hv.z * w1.z + hv.w * w1.w;
    float b = hv.x * w2.x + hv.y * w2.y + hv.z * w2.z + hv.w * w2.w;
    #pragma unroll
    for (int o = 16; o > 0; o >>= 1) {
        a += __shfl_down_sync(0xffffffffu, a, o);
        b += __shfl_down_sync(0xffffffffu, b, o);
    }
    if (lane == 0) { g_p[warp] = a; g_q[warp] = b; }
}

// ---------------- gathered SpMM per layer: hn = EPS*raw + A(g) @ h --------
__global__ __launch_bounds__(256)
void k_agg(const float* __restrict__ h, float* __restrict__ hn,
           const float* __restrict__ gbp, int kidx) {
    int gt = blockIdx.x * blockDim.x + threadIdx.x;
    int warp = gt >> 5, lane = gt & 31;
    if (warp >= N_NODES) return;
    float gb = __ldg(&gbp[kidx]);
    int beg = g_indptr[warp], end = g_indptr[warp + 1];
    float qc = g_q[warp];
    float4 r = ((const float4*)g_raw)[warp * 32 + lane];
    float4 acc = make_float4(EPS_V * r.x, EPS_V * r.y, EPS_V * r.z, EPS_V * r.w);
    const float4* h4 = (const float4*)h;

    for (int e = beg; e < end; e += 32) {
        int idx = e + lane;
        int src = 0; float nrm = 0.f;
        if (idx < end) {
            src = g_esrc[idx];
            nrm = tanhf(g_p[src] + qc + gb) * g_ew[idx];
        }
        int m = end - e; if (m > 32) m = 32;
        for (int j = 0; j < m; j++) {
            int   s  = __shfl_sync(0xffffffffu, src, j);
            float nm = __shfl_sync(0xffffffffu, nrm, j);
            float4 hv = h4[(size_t)s * 32 + lane];
            acc.x = fmaf(nm, hv.x, acc.x);
            acc.y = fmaf(nm, hv.y, acc.y);
            acc.z = fmaf(nm, hv.z, acc.z);
            acc.w = fmaf(nm, hv.w, acc.w);
        }
    }
    ((float4*)hn)[warp * 32 + lane] = acc;
}

// ---------------- classifier + log_softmax: [N,128]x[40,128]^T ------------
__global__ __launch_bounds__(320)
void k_out(const float* __restrict__ h, const float* __restrict__ w,
           const float* __restrict__ b, float* __restrict__ out, int n) {
    __shared__ float ws[N_CLS * HID];
    __shared__ float hs[8 * HID];
    __shared__ float logits[8 * N_CLS];
    int tid = threadIdx.x;
    for (int i = tid; i < N_CLS * HID; i += blockDim.x) ws[i] = w[i];
    int nodeBase = blockIdx.x * 8;
    for (int i = tid; i < 8 * HID; i += blockDim.x) {
        int nn = nodeBase + i / HID;
        hs[i] = (nn < n) ? h[(size_t)nn * HID + (i % HID)] : 0.f;
    }
    __syncthreads();

    int ln = tid / N_CLS;
    int c  = tid % N_CLS;
    float accv = b[c];
    const float4* hp = (const float4*)&hs[ln * HID];
    const float4* wp = (const float4*)&ws[c * HID];
    #pragma unroll
    for (int k = 0; k < HID / 4; k++) {
        float4 hv = hp[k], wv = wp[k];
        accv = fmaf(hv.x, wv.x, accv);
        accv = fmaf(hv.y, wv.y, accv);
        accv = fmaf(hv.z, wv.z, accv);
        accv = fmaf(hv.w, wv.w, accv);
    }
    logits[ln * N_CLS + c] = accv;
    __syncthreads();

    float mx = -1e30f;
    #pragma unroll 8
    for (int j = 0; j < N_CLS; j++) mx = fmaxf(mx, logits[ln * N_CLS + j]);
    float s = 0.f;
    #pragma unroll 8
    for (int j = 0; j < N_CLS; j++) s += expf(logits[ln * N_CLS + j] - mx);
    int nn = nodeBase + ln;
    if (nn < n) out[(size_t)nn * N_CLS + c] = accv - mx - logf(s);
}

// ---------------- host launcher ----------------
extern "C" void kernel_launch(void* const* d_in, const int* in_sizes, int n_in,
                              void* d_out, int out_size) {
    const float* x   = (const float*)d_in[0];
    const int*   ei  = (const int*)d_in[1];
    const float* t1w = (const float*)d_in[2];
    const float* t1b = (const float*)d_in[3];
    const float* gw  = (const float*)d_in[4];
    const float* gb  = (const float*)d_in[5];
    const float* t2w = (const float*)d_in[6];
    const float* t2b = (const float*)d_in[7];
    float* out = (float*)d_out;

    const int* row = ei;
    const int* col = ei + N_EDGES;

    float *hA, *hB, *raw;
    cudaGetSymbolAddress((void**)&hA,  g_hA);
    cudaGetSymbolAddress((void**)&hB,  g_hB);
    cudaGetSymbolAddress((void**)&raw, g_raw);

    const int scanBlocks = (N_NODES + 255) / 256;  // 196

    // CSR build
    k_zero_counts<<<(N_NODES + 255) / 256, 256>>>();
    k_count<<<(N_EDGES + 255) / 256, 256>>>(row, col);
    k_nd<<<(N_NODES + 255) / 256, 256>>>();
    k_scan1<<<scanBlocks, 256>>>();
    k_scan2<<<1, 256>>>(scanBlocks);
    k_scan3<<<scanBlocks, 256>>>();
    k_scatter<<<(N_EDGES + 255) / 256, 256>>>(row, col);

    // h = relu(x @ t1_w^T + b); raw = h   (HMMA bf16 hi/lo split)
    k_gemm1_mma<<<(N_NODES + 127) / 128, 256>>>(x, t1w, t1b, hA, raw, N_NODES);

    // 4 propagation layers (ping-pong hA/hB)
    float* cur = hA;
    float* nxt = hB;
    int warpBlocks = (N_NODES * 32 + 255) / 256;
    for (int k = 0; k < 4; k++) {
        k_pq<<<warpBlocks, 256>>>(cur, gw + (size_t)k * 2 * HID);
        k_agg<<<warpBlocks, 256>>>(cur, nxt, gb, k);
        float* t = cur; cur = nxt; nxt = t;
    }

    // classifier + log_softmax
    k_out<<<(N_NODES + 7) / 8, 320>>>(cur, t2w, t2b, out, N_NODES);
}

// round 5
// speedup vs baseline: 1.3976x; 1.0698x over previous
#include <cuda_runtime.h>
#include <cuda_bf16.h>
#include <cuda_fp16.h>
#include <math.h>
#include <stdint.h>

#define N_NODES 50000
#define N_EDGES 800000
#define F_INN   512
#define HID     128
#define N_CLS   40
#define EPS_V   0.3f

// ---------------- scratch (static device globals; no allocations) ----------
__device__ float  g_raw[N_NODES * HID];       // fp32 layer-0 residual
__device__ __half g_hA [N_NODES * HID];       // fp16 gathered features (ping)
__device__ __half g_hB [N_NODES * HID];       // fp16 gathered features (pong)
__device__ float  g_pA [N_NODES];             // gate dots, double-buffered
__device__ float  g_qA [N_NODES];
__device__ float  g_pB [N_NODES];
__device__ float  g_qB [N_NODES];
__device__ float  g_nd [N_NODES];
__device__ float  g_ew [N_EDGES];
__device__ int    g_esrc[N_EDGES];
__device__ int    g_indptr[N_NODES + 1];
__device__ int    g_cnt[N_NODES];
__device__ int    g_deg[N_NODES];
__device__ int    g_cursor[N_NODES];
__device__ int    g_bsum[256];
__device__ int    g_boff[256];

// ================= PTX helpers (ldmatrix / mma.sync — baseline sm_80+) =====
__device__ __forceinline__ uint32_t smem_u32(const void* p) {
    uint32_t a;
    asm("{ .reg .u64 t; cvta.to.shared.u64 t, %1; cvt.u32.u64 %0, t; }" : "=r"(a) : "l"(p));
    return a;
}
__device__ __forceinline__ void ldsm_x4(uint32_t (&r)[4], uint32_t addr) {
    asm volatile("ldmatrix.sync.aligned.m8n8.x4.shared.b16 {%0,%1,%2,%3}, [%4];"
        : "=r"(r[0]), "=r"(r[1]), "=r"(r[2]), "=r"(r[3]) : "r"(addr));
}
__device__ __forceinline__ void ldsm_x2(uint32_t (&r)[2], uint32_t addr) {
    asm volatile("ldmatrix.sync.aligned.m8n8.x2.shared.b16 {%0,%1}, [%2];"
        : "=r"(r[0]), "=r"(r[1]) : "r"(addr));
}
__device__ __forceinline__ void mma_bf16(float (&d)[4], const uint32_t (&a)[4], const uint32_t (&b)[2]) {
    asm volatile("mma.sync.aligned.m16n8k16.row.col.f32.bf16.bf16.f32 "
        "{%0,%1,%2,%3}, {%4,%5,%6,%7}, {%8,%9}, {%0,%1,%2,%3};"
        : "+f"(d[0]), "+f"(d[1]), "+f"(d[2]), "+f"(d[3])
        : "r"(a[0]), "r"(a[1]), "r"(a[2]), "r"(a[3]), "r"(b[0]), "r"(b[1]));
}
__device__ __forceinline__ uint32_t pack_bf16(float a, float b) {
    __nv_bfloat16 x = __float2bfloat16(a), y = __float2bfloat16(b);
    return (uint32_t)(*(uint16_t*)&x) | ((uint32_t)(*(uint16_t*)&y) << 16);
}

// ---------------- CSR build ----------------
__global__ void k_zero_counts() {
    int i = blockIdx.x * blockDim.x + threadIdx.x;
    if (i < N_NODES) { g_cnt[i] = 0; g_deg[i] = 0; }
}

__global__ void k_count(const int* __restrict__ row, const int* __restrict__ col) {
    int e = blockIdx.x * blockDim.x + threadIdx.x;
    if (e < N_EDGES) {
        atomicAdd(&g_deg[row[e]], 1);
        atomicAdd(&g_cnt[col[e]], 1);
    }
}

__global__ void k_scan1() {
    __shared__ int s[256];
    int tid = threadIdx.x;
    int i = blockIdx.x * 256 + tid;
    int v = (i < N_NODES) ? g_cnt[i] : 0;
    s[tid] = v;
    __syncthreads();
    #pragma unroll
    for (int off = 1; off < 256; off <<= 1) {
        int t = (tid >= off) ? s[tid - off] : 0;
        __syncthreads();
        s[tid] += t;
        __syncthreads();
    }
    if (i < N_NODES) g_indptr[i] = s[tid] - v;
    if (tid == 255) g_bsum[blockIdx.x] = s[255];
}

__global__ void k_scan2(int nblocks) {
    __shared__ int s[256];
    int tid = threadIdx.x;
    int v = (tid < nblocks) ? g_bsum[tid] : 0;
    s[tid] = v;
    __syncthreads();
    #pragma unroll
    for (int off = 1; off < 256; off <<= 1) {
        int t = (tid >= off) ? s[tid - off] : 0;
        __syncthreads();
        s[tid] += t;
        __syncthreads();
    }
    g_boff[tid] = s[tid] - v;
    if (tid == 0) g_indptr[N_NODES] = N_EDGES;
}

// scan fixup + cursor init + degree norm (fused)
__global__ void k_scan3_nd() {
    int tid = threadIdx.x;
    int i = blockIdx.x * 256 + tid;
    if (i < N_NODES) {
        int ip = g_indptr[i] + g_boff[blockIdx.x];
        g_indptr[i] = ip;
        g_cursor[i] = ip;
        int d = g_deg[i];
        g_nd[i] = rsqrtf((float)(d < 1 ? 1 : d));
    }
}

__global__ void k_scatter(const int* __restrict__ row, const int* __restrict__ col) {
    int e = blockIdx.x * blockDim.x + threadIdx.x;
    if (e < N_EDGES) {
        int r = row[e], c = col[e];
        int pos = atomicAdd(&g_cursor[c], 1);
        g_esrc[pos] = r;
        g_ew[pos] = g_nd[r] * g_nd[c];
    }
}

// ============ GEMM1 via mma.sync bf16 hi/lo split, reg-prefetch pipeline ===
#define TSTRIDE 40

__global__ __launch_bounds__(256)
void k_gemm1_mma(const float* __restrict__ A, const float* __restrict__ W,
                 const float* __restrict__ bias,
                 __half* __restrict__ h, float* __restrict__ raw, int n) {
    __shared__ uint16_t As_hi[128 * TSTRIDE];
    __shared__ uint16_t As_lo[128 * TSTRIDE];
    __shared__ uint16_t Ws_hi[128 * TSTRIDE];
    __shared__ uint16_t Ws_lo[128 * TSTRIDE];
    __shared__ float sbias[HID];

    int tid = threadIdx.x;
    int wid = tid >> 5, lane = tid & 31;
    int warp_m = wid >> 2;
    int warp_n = wid & 3;
    int blockM = blockIdx.x * 128;

    if (tid < HID) sbias[tid] = bias[tid];

    uint32_t sAh = smem_u32(As_hi), sAl = smem_u32(As_lo);
    uint32_t sWh = smem_u32(Ws_hi), sWl = smem_u32(Ws_lo);

    float acc[4][4][4];
    #pragma unroll
    for (int i = 0; i < 4; i++)
        #pragma unroll
        for (int j = 0; j < 4; j++)
            #pragma unroll
            for (int k = 0; k < 4; k++) acc[i][j][k] = 0.f;

    int a_row = (lane & 15), a_cblk = (lane >> 4) * 8;
    int b_row = (lane & 7), b_cblk = ((lane >> 3) & 1) * 8;

    int lr  = tid >> 3;            // 0..31 base row (stride 32 over 4 its)
    int lc4 = (tid & 7) * 4;       // col 0..28

    float4 aReg[4], wReg[4];
    #pragma unroll
    for (int it = 0; it < 4; it++) {
        int r = lr + it * 32;
        int gr = blockM + r;
        aReg[it] = (gr < n) ? *(const float4*)&A[(size_t)gr * F_INN + lc4]
                            : make_float4(0.f, 0.f, 0.f, 0.f);
        wReg[it] = *(const float4*)&W[(size_t)r * F_INN + lc4];
    }

    for (int ch = 0; ch < 16; ch++) {
        #pragma unroll
        for (int it = 0; it < 4; it++) {
            int r = lr + it * 32;
            int soff = r * TSTRIDE + lc4;
            float4 av = aReg[it];
            float hx = __bfloat162float(__float2bfloat16(av.x));
            float hy = __bfloat162float(__float2bfloat16(av.y));
            float hz = __bfloat162float(__float2bfloat16(av.z));
            float hw = __bfloat162float(__float2bfloat16(av.w));
            *(uint2*)&As_hi[soff] = make_uint2(pack_bf16(av.x, av.y), pack_bf16(av.z, av.w));
            *(uint2*)&As_lo[soff] = make_uint2(pack_bf16(av.x - hx, av.y - hy), pack_bf16(av.z - hz, av.w - hw));

            float4 wv = wReg[it];
            hx = __bfloat162float(__float2bfloat16(wv.x));
            hy = __bfloat162float(__float2bfloat16(wv.y));
            hz = __bfloat162float(__float2bfloat16(wv.z));
            hw = __bfloat162float(__float2bfloat16(wv.w));
            *(uint2*)&Ws_hi[soff] = make_uint2(pack_bf16(wv.x, wv.y), pack_bf16(wv.z, wv.w));
            *(uint2*)&Ws_lo[soff] = make_uint2(pack_bf16(wv.x - hx, wv.y - hy), pack_bf16(wv.z - hz, wv.w - hw));
        }
        __syncthreads();

        if (ch < 15) {
            int k0n = (ch + 1) * 32;
            #pragma unroll
            for (int it = 0; it < 4; it++) {
                int r = lr + it * 32;
                int gr = blockM + r;
                aReg[it] = (gr < n) ? *(const float4*)&A[(size_t)gr * F_INN + k0n + lc4]
                                    : make_float4(0.f, 0.f, 0.f, 0.f);
                wReg[it] = *(const float4*)&W[(size_t)r * F_INN + k0n + lc4];
            }
        }

        #pragma unroll
        for (int kk = 0; kk < 32; kk += 16) {
            uint32_t bh[4][2], bl[4][2];
            #pragma unroll
            for (int nt = 0; nt < 4; nt++) {
                uint32_t boff = 2u * (uint32_t)((warp_n * 32 + nt * 8 + b_row) * TSTRIDE + kk + b_cblk);
                ldsm_x2(bh[nt], sWh + boff);
                ldsm_x2(bl[nt], sWl + boff);
            }
            #pragma unroll
            for (int mt = 0; mt < 4; mt++) {
                uint32_t aoff = 2u * (uint32_t)((warp_m * 64 + mt * 16 + a_row) * TSTRIDE + kk + a_cblk);
                uint32_t ah[4], al[4];
                ldsm_x4(ah, sAh + aoff);
                ldsm_x4(al, sAl + aoff);
                #pragma unroll
                for (int nt = 0; nt < 4; nt++) {
                    mma_bf16(acc[mt][nt], ah, bh[nt]);
                    mma_bf16(acc[mt][nt], ah, bl[nt]);
                    mma_bf16(acc[mt][nt], al, bh[nt]);
                }
            }
        }
        __syncthreads();
    }

    #pragma unroll
    for (int mt = 0; mt < 4; mt++) {
        int m0 = blockM + warp_m * 64 + mt * 16 + (lane >> 2);
        int m1 = m0 + 8;
        #pragma unroll
        for (int nt = 0; nt < 4; nt++) {
            int n0 = warp_n * 32 + nt * 8 + 2 * (lane & 3);
            float b0 = sbias[n0], b1 = sbias[n0 + 1];
            if (m0 < n) {
                float vx = fmaxf(acc[mt][nt][0] + b0, 0.f);
                float vy = fmaxf(acc[mt][nt][1] + b1, 0.f);
                *(float2*)&raw[(size_t)m0 * HID + n0] = make_float2(vx, vy);
                *(__half2*)&h[(size_t)m0 * HID + n0] = __floats2half2_rn(vx, vy);
            }
            if (m1 < n) {
                float vx = fmaxf(acc[mt][nt][2] + b0, 0.f);
                float vy = fmaxf(acc[mt][nt][3] + b1, 0.f);
                *(float2*)&raw[(size_t)m1 * HID + n0] = make_float2(vx, vy);
                *(__half2*)&h[(size_t)m1 * HID + n0] = __floats2half2_rn(vx, vy);
            }
        }
    }
}

// ---------------- layer-0 gate dots (from fp32 raw) -----------------------
__global__ __launch_bounds__(256)
void k_pq(const float* __restrict__ hraw, const float* __restrict__ gw,
          float* __restrict__ p, float* __restrict__ q) {
    int gt = blockIdx.x * blockDim.x + threadIdx.x;
    int warp = gt >> 5, lane = gt & 31;
    if (warp >= N_NODES) return;
    float4 hv = ((const float4*)hraw)[warp * 32 + lane];
    float4 w1 = ((const float4*)gw)[lane];
    float4 w2 = ((const float4*)gw)[32 + lane];
    float a = hv.x * w1.x + hv.y * w1.y + hv.z * w1.z + hv.w * w1.w;
    float b = hv.x * w2.x + hv.y * w2.y + hv.z * w2.z + hv.w * w2.w;
    #pragma unroll
    for (int o = 16; o > 0; o >>= 1) {
        a += __shfl_down_sync(0xffffffffu, a, o);
        b += __shfl_down_sync(0xffffffffu, b, o);
    }
    if (lane == 0) { p[warp] = a; q[warp] = b; }
}

// ------- gathered SpMM per layer + fused next-layer gate dots -------------
// reads p/q from pq_in, writes next layer's to pq_out (double-buffered: no race)
__global__ __launch_bounds__(256)
void k_agg(const __half* __restrict__ h, __half* __restrict__ hn,
           const float* __restrict__ gbp, int kidx,
           const float* __restrict__ p_in, const float* __restrict__ q_in,
           float* __restrict__ p_out, float* __restrict__ q_out,
           const float* __restrict__ gw_next) {
    int gt = blockIdx.x * blockDim.x + threadIdx.x;
    int warp = gt >> 5, lane = gt & 31;
    if (warp >= N_NODES) return;
    float gb = __ldg(&gbp[kidx]);
    int beg = g_indptr[warp], end = g_indptr[warp + 1];
    float qc = q_in[warp];
    float4 r = ((const float4*)g_raw)[warp * 32 + lane];
    float4 acc = make_float4(EPS_V * r.x, EPS_V * r.y, EPS_V * r.z, EPS_V * r.w);
    const uint2* h2 = (const uint2*)h;

    for (int e = beg; e < end; e += 32) {
        int idx = e + lane;
        int src = 0; float nrm = 0.f;
        if (idx < end) {
            src = g_esrc[idx];
            nrm = tanhf(p_in[src] + qc + gb) * g_ew[idx];
        }
        int m = end - e; if (m > 32) m = 32;
        for (int j = 0; j < m; j++) {
            int   s  = __shfl_sync(0xffffffffu, src, j);
            float nm = __shfl_sync(0xffffffffu, nrm, j);
            uint2 hv = h2[(size_t)s * 32 + lane];
            float2 f01 = __half22float2(*(__half2*)&hv.x);
            float2 f23 = __half22float2(*(__half2*)&hv.y);
            acc.x = fmaf(nm, f01.x, acc.x);
            acc.y = fmaf(nm, f01.y, acc.y);
            acc.z = fmaf(nm, f23.x, acc.z);
            acc.w = fmaf(nm, f23.y, acc.w);
        }
    }
    uint2 packed;
    *(__half2*)&packed.x = __floats2half2_rn(acc.x, acc.y);
    *(__half2*)&packed.y = __floats2half2_rn(acc.z, acc.w);
    ((uint2*)hn)[warp * 32 + lane] = packed;

    // fused: next layer's gate dots (into the OTHER pq buffer)
    if (gw_next) {
        float4 w1 = ((const float4*)gw_next)[lane];
        float4 w2 = ((const float4*)gw_next)[32 + lane];
        float a = acc.x * w1.x + acc.y * w1.y + acc.z * w1.z + acc.w * w1.w;
        float b = acc.x * w2.x + acc.y * w2.y + acc.z * w2.z + acc.w * w2.w;
        #pragma unroll
        for (int o = 16; o > 0; o >>= 1) {
            a += __shfl_down_sync(0xffffffffu, a, o);
            b += __shfl_down_sync(0xffffffffu, b, o);
        }
        if (lane == 0) { p_out[warp] = a; q_out[warp] = b; }
    }
}

// ---------------- classifier + log_softmax: [N,128]x[40,128]^T ------------
__global__ __launch_bounds__(320)
void k_out(const __half* __restrict__ h, const float* __restrict__ w,
           const float* __restrict__ b, float* __restrict__ out, int n) {
    __shared__ float ws[N_CLS * HID];
    __shared__ float hs[8 * HID];
    __shared__ float logits[8 * N_CLS];
    int tid = threadIdx.x;
    for (int i = tid; i < N_CLS * HID; i += blockDim.x) ws[i] = w[i];
    int nodeBase = blockIdx.x * 8;
    for (int i = tid; i < 8 * HID; i += blockDim.x) {
        int nn = nodeBase + i / HID;
        hs[i] = (nn < n) ? __half2float(h[(size_t)nn * HID + (i % HID)]) : 0.f;
    }
    __syncthreads();

    int ln = tid / N_CLS;
    int c  = tid % N_CLS;
    float accv = b[c];
    const float4* hp = (const float4*)&hs[ln * HID];
    const float4* wp = (const float4*)&ws[c * HID];
    #pragma unroll
    for (int k = 0; k < HID / 4; k++) {
        float4 hv = hp[k], wv = wp[k];
        accv = fmaf(hv.x, wv.x, accv);
        accv = fmaf(hv.y, wv.y, accv);
        accv = fmaf(hv.z, wv.z, accv);
        accv = fmaf(hv.w, wv.w, accv);
    }
    logits[ln * N_CLS + c] = accv;
    __syncthreads();

    float mx = -1e30f;
    #pragma unroll 8
    for (int j = 0; j < N_CLS; j++) mx = fmaxf(mx, logits[ln * N_CLS + j]);
    float s = 0.f;
    #pragma unroll 8
    for (int j = 0; j < N_CLS; j++) s += expf(logits[ln * N_CLS + j] - mx);
    int nn = nodeBase + ln;
    if (nn < n) out[(size_t)nn * N_CLS + c] = accv - mx - logf(s);
}

// ---------------- host launcher ----------------
extern "C" void kernel_launch(void* const* d_in, const int* in_sizes, int n_in,
                              void* d_out, int out_size) {
    const float* x   = (const float*)d_in[0];
    const int*   ei  = (const int*)d_in[1];
    const float* t1w = (const float*)d_in[2];
    const float* t1b = (const float*)d_in[3];
    const float* gw  = (const float*)d_in[4];
    const float* gb  = (const float*)d_in[5];
    const float* t2w = (const float*)d_in[6];
    const float* t2b = (const float*)d_in[7];
    float* out = (float*)d_out;

    const int* row = ei;
    const int* col = ei + N_EDGES;

    __half *hA, *hB;
    float *raw, *pA, *qA, *pB, *qB;
    cudaGetSymbolAddress((void**)&hA,  g_hA);
    cudaGetSymbolAddress((void**)&hB,  g_hB);
    cudaGetSymbolAddress((void**)&raw, g_raw);
    cudaGetSymbolAddress((void**)&pA,  g_pA);
    cudaGetSymbolAddress((void**)&qA,  g_qA);
    cudaGetSymbolAddress((void**)&pB,  g_pB);
    cudaGetSymbolAddress((void**)&qB,  g_qB);

    const int scanBlocks = (N_NODES + 255) / 256;  // 196

    // CSR build
    k_zero_counts<<<(N_NODES + 255) / 256, 256>>>();
    k_count<<<(N_EDGES + 255) / 256, 256>>>(row, col);
    k_scan1<<<scanBlocks, 256>>>();
    k_scan2<<<1, 256>>>(scanBlocks);
    k_scan3_nd<<<scanBlocks, 256>>>();
    k_scatter<<<(N_EDGES + 255) / 256, 256>>>(row, col);

    // h = relu(x @ t1_w^T + b)  (HMMA bf16 hi/lo split, reg-prefetch pipeline)
    k_gemm1_mma<<<(N_NODES + 127) / 128, 256>>>(x, t1w, t1b, hA, raw, N_NODES);

    int warpBlocks = (N_NODES * 32 + 255) / 256;
    // layer-0 gates from fp32 raw (== h at layer 0)
    k_pq<<<warpBlocks, 256>>>(raw, gw, pA, qA);

    // 4 propagation layers (ping-pong hA/hB and pq buffers)
    __half* cur = hA;
    __half* nxt = hB;
    for (int k = 0; k < 4; k++) {
        const float* gwn = (k < 3) ? (gw + (size_t)(k + 1) * 2 * HID) : (const float*)0;
        float* pi = (k & 1) ? pB : pA;
        float* qi = (k & 1) ? qB : qA;
        float* po = (k & 1) ? pA : pB;
        float* qo = (k & 1) ? qA : qB;
        k_agg<<<warpBlocks, 256>>>(cur, nxt, gb, k, pi, qi, po, qo, gwn);
        __half* t = cur; cur = nxt; nxt = t;
    }

    // classifier + log_softmax
    k_out<<<(N_NODES + 7) / 8, 320>>>(cur, t2w, t2b, out, N_NODES);
}